// round 2
// baseline (speedup 1.0000x reference)
#include <cuda_runtime.h>
#include <cstdint>

// KDPointToPointLoss: loss[b] = (1/(3N)) * sum_n min_m ||s[b,:,n] - t[b,:,m]||^2
// B=8, C=3, N=M=4096 (fixed by dataset).
//
// Strategy: score(n,m) = |t_m|^2 - 2 s_n . t_m  (= d2 - |s_n|^2, monotone in d2).
// Targets stored in smem as packed f32x2 pairs; inner loop uses fma.rn.f32x2
// (FFMA2, 2 fp32 FMAs per issue slot — only reachable via PTX).
// Each block owns 256 source points and scans ALL targets -> no init pass,
// no atomics; per-point min written directly, tiny deterministic reduce after.

#define BATCH 8
#define NPTS  4096
#define MPTS  4096

#define THREADS   128
#define ILP       2                       // source points per thread
#define SRC_PER_BLOCK (THREADS * ILP)     // 256
#define SRC_CHUNKS (NPTS / SRC_PER_BLOCK) // 16
#define TC        1024                    // targets per smem chunk
#define TC2       (TC / 2)                // packed pairs per chunk
#define NCHUNK    (MPTS / TC)             // 4

__device__ float g_d2[BATCH * NPTS];      // per-(batch, source) min squared distance

__device__ __forceinline__ unsigned long long ffma2(
    unsigned long long a, unsigned long long b, unsigned long long c) {
    unsigned long long d;
    asm("fma.rn.f32x2 %0, %1, %2, %3;" : "=l"(d) : "l"(a), "l"(b), "l"(c));
    return d;
}
__device__ __forceinline__ unsigned long long pack2(float lo, float hi) {
    unsigned long long r;
    asm("mov.b64 %0, {%1, %2};" : "=l"(r) : "f"(lo), "f"(hi));
    return r;
}
__device__ __forceinline__ void unpack2(unsigned long long v, float& lo, float& hi) {
    asm("mov.b64 {%0, %1}, %2;" : "=f"(lo), "=f"(hi) : "l"(v));
}

__global__ __launch_bounds__(THREADS) void nn_kernel(
    const float* __restrict__ src, const float* __restrict__ tgt) {
    // Packed target chunk: {x_j,x_j+1}, {y...}, {z...}, {|t|^2 ...}
    __shared__ unsigned long long sx2[TC2], sy2[TC2], sz2[TC2], sw2[TC2];

    const int b    = blockIdx.y;
    const int src0 = blockIdx.x * SRC_PER_BLOCK;
    const int tid  = threadIdx.x;

    // Per-thread source points: packed duplicated coefficients (-2s, -2s).
    const float* sb = src + (size_t)b * 3 * NPTS;
    unsigned long long cx2[ILP], cy2[ILP], cz2[ILP];
    float s2[ILP], mnLo[ILP], mnHi[ILP];
#pragma unroll
    for (int p = 0; p < ILP; p++) {
        int n = src0 + p * THREADS + tid;
        float sx = sb[0 * NPTS + n];
        float sy = sb[1 * NPTS + n];
        float sz = sb[2 * NPTS + n];
        cx2[p] = pack2(-2.0f * sx, -2.0f * sx);
        cy2[p] = pack2(-2.0f * sy, -2.0f * sy);
        cz2[p] = pack2(-2.0f * sz, -2.0f * sz);
        s2[p]  = fmaf(sx, sx, fmaf(sy, sy, sz * sz));
        mnLo[p] = 1e30f;
        mnHi[p] = 1e30f;
    }

    const float2* tx = (const float2*)(tgt + (size_t)b * 3 * MPTS + 0 * MPTS);
    const float2* ty = (const float2*)(tgt + (size_t)b * 3 * MPTS + 1 * MPTS);
    const float2* tz = (const float2*)(tgt + (size_t)b * 3 * MPTS + 2 * MPTS);

    for (int ch = 0; ch < NCHUNK; ch++) {
        const int base2 = ch * TC2;
        __syncthreads();
        // Cooperative packed load: thread handles pair j2 -> fully coalesced float2.
        for (int j2 = tid; j2 < TC2; j2 += THREADS) {
            float2 x = tx[base2 + j2];
            float2 y = ty[base2 + j2];
            float2 z = tz[base2 + j2];
            float w0 = fmaf(x.x, x.x, fmaf(y.x, y.x, z.x * z.x));
            float w1 = fmaf(x.y, x.y, fmaf(y.y, y.y, z.y * z.y));
            sx2[j2] = pack2(x.x, x.y);
            sy2[j2] = pack2(y.x, y.y);
            sz2[j2] = pack2(z.x, z.y);
            sw2[j2] = pack2(w0, w1);
        }
        __syncthreads();

        // Main loop: per (point, target-pair): 3 FFMA2 + 2 FMNMX.
        // smem loads are warp-uniform broadcasts (LDS.64, conflict-free).
#pragma unroll 8
        for (int j2 = 0; j2 < TC2; j2++) {
            unsigned long long vx = sx2[j2];
            unsigned long long vy = sy2[j2];
            unsigned long long vz = sz2[j2];
            unsigned long long vw = sw2[j2];
#pragma unroll
            for (int p = 0; p < ILP; p++) {
                unsigned long long acc = ffma2(cz2[p], vz, vw);
                acc = ffma2(cy2[p], vy, acc);
                acc = ffma2(cx2[p], vx, acc);
                float lo, hi;
                unpack2(acc, lo, hi);
                mnLo[p] = fminf(mnLo[p], lo);
                mnHi[p] = fminf(mnHi[p], hi);
            }
        }
    }

    // Final per-point squared distance (block covered ALL targets -> direct store).
#pragma unroll
    for (int p = 0; p < ILP; p++) {
        int n = src0 + p * THREADS + tid;
        g_d2[b * NPTS + n] = fminf(mnLo[p], mnHi[p]) + s2[p];
    }
}

__global__ void reduce_kernel(float* __restrict__ out) {
    __shared__ float sh[256];
    const int b = blockIdx.x;
    float s = 0.0f;
    for (int i = threadIdx.x; i < NPTS; i += 256)
        s += g_d2[b * NPTS + i];
    sh[threadIdx.x] = s;
    __syncthreads();
    for (int o = 128; o > 0; o >>= 1) {
        if (threadIdx.x < o) sh[threadIdx.x] += sh[threadIdx.x + o];
        __syncthreads();
    }
    if (threadIdx.x == 0) out[b] = sh[0] * (1.0f / (3.0f * NPTS));
}

extern "C" void kernel_launch(void* const* d_in, const int* in_sizes, int n_in,
                              void* d_out, int out_size) {
    const float* src = (const float*)d_in[0];  // [B,3,N]
    const float* tgt = (const float*)d_in[1];  // [B,3,M]
    float* out = (float*)d_out;                // [B]

    dim3 grid(SRC_CHUNKS, BATCH);              // 16 x 8 = 128 blocks
    nn_kernel<<<grid, THREADS>>>(src, tgt);
    reduce_kernel<<<BATCH, 256>>>(out);
}

// round 3
// speedup vs baseline: 1.6937x; 1.6937x over previous
#include <cuda_runtime.h>
#include <cstdint>

// KDPointToPointLoss: loss[b] = (1/(3N)) * sum_n min_m ||s[b,:,n] - t[b,:,m]||^2
// B=8, C=3, N=M=4096 (fixed by dataset).
//
// score(n,m) = |t_m|^2 - 2 s_n.t_m (monotone in d2). Targets packed in smem as
// f32x2 pairs; inner loop uses fma.rn.f32x2 (FFMA2: 2 fp32 FMAs/issue slot).
// Grid splits (tgt x src x batch) = 8x8x8 = 512 blocks for occupancy; each
// block writes its partial min to a private slot -> no init pass, no atomics,
// deterministic. Reduce kernel mins the 8 partials and sums per batch.

#define BATCH 8
#define NPTS  4096
#define MPTS  4096

#define THREADS   128
#define ILP       4                       // source points per thread
#define SRC_PER_BLOCK (THREADS * ILP)     // 512
#define SRC_CHUNKS (NPTS / SRC_PER_BLOCK) // 8
#define TSPLIT    8                       // target splits
#define TC        (MPTS / TSPLIT)         // 512 targets per block
#define TC2       (TC / 2)                // 256 packed pairs

// Partial per-(tsplit, batch, source) min score (without +|s|^2 yet is fine;
// we add s2 at store time so the reduce is a plain min).
__device__ float g_part[TSPLIT * BATCH * NPTS];

__device__ __forceinline__ unsigned long long ffma2(
    unsigned long long a, unsigned long long b, unsigned long long c) {
    unsigned long long d;
    asm("fma.rn.f32x2 %0, %1, %2, %3;" : "=l"(d) : "l"(a), "l"(b), "l"(c));
    return d;
}
__device__ __forceinline__ unsigned long long pack2(float lo, float hi) {
    unsigned long long r;
    asm("mov.b64 %0, {%1, %2};" : "=l"(r) : "f"(lo), "f"(hi));
    return r;
}
__device__ __forceinline__ void unpack2(unsigned long long v, float& lo, float& hi) {
    asm("mov.b64 {%0, %1}, %2;" : "=f"(lo), "=f"(hi) : "l"(v));
}

__global__ __launch_bounds__(THREADS) void nn_kernel(
    const float* __restrict__ src, const float* __restrict__ tgt) {
    __shared__ unsigned long long sx2[TC2], sy2[TC2], sz2[TC2], sw2[TC2];

    const int ts   = blockIdx.x;               // target split
    const int src0 = blockIdx.y * SRC_PER_BLOCK;
    const int b    = blockIdx.z;
    const int tid  = threadIdx.x;
    const int tgt0 = ts * TC;

    // Cooperative packed load of this target chunk.
    const float2* tx = (const float2*)(tgt + (size_t)b * 3 * MPTS + 0 * MPTS + tgt0);
    const float2* ty = (const float2*)(tgt + (size_t)b * 3 * MPTS + 1 * MPTS + tgt0);
    const float2* tz = (const float2*)(tgt + (size_t)b * 3 * MPTS + 2 * MPTS + tgt0);
    for (int j2 = tid; j2 < TC2; j2 += THREADS) {
        float2 x = tx[j2];
        float2 y = ty[j2];
        float2 z = tz[j2];
        float w0 = fmaf(x.x, x.x, fmaf(y.x, y.x, z.x * z.x));
        float w1 = fmaf(x.y, x.y, fmaf(y.y, y.y, z.y * z.y));
        sx2[j2] = pack2(x.x, x.y);
        sy2[j2] = pack2(y.x, y.y);
        sz2[j2] = pack2(z.x, z.y);
        sw2[j2] = pack2(w0, w1);
    }

    // Per-thread source points: packed duplicated coefficients (-2s, -2s).
    const float* sb = src + (size_t)b * 3 * NPTS;
    unsigned long long cx2[ILP], cy2[ILP], cz2[ILP];
    float s2[ILP], mnLo[ILP], mnHi[ILP];
#pragma unroll
    for (int p = 0; p < ILP; p++) {
        int n = src0 + p * THREADS + tid;
        float sx = sb[0 * NPTS + n];
        float sy = sb[1 * NPTS + n];
        float sz = sb[2 * NPTS + n];
        cx2[p] = pack2(-2.0f * sx, -2.0f * sx);
        cy2[p] = pack2(-2.0f * sy, -2.0f * sy);
        cz2[p] = pack2(-2.0f * sz, -2.0f * sz);
        s2[p]  = fmaf(sx, sx, fmaf(sy, sy, sz * sz));
        mnLo[p] = 1e30f;
        mnHi[p] = 1e30f;
    }
    __syncthreads();

    // Main loop: per j2 (2 targets): 4 LDS.64 + ILP*(3 FFMA2 + 2 FMNMX).
#pragma unroll 4
    for (int j2 = 0; j2 < TC2; j2++) {
        unsigned long long vx = sx2[j2];
        unsigned long long vy = sy2[j2];
        unsigned long long vz = sz2[j2];
        unsigned long long vw = sw2[j2];
#pragma unroll
        for (int p = 0; p < ILP; p++) {
            unsigned long long acc = ffma2(cz2[p], vz, vw);
            acc = ffma2(cy2[p], vy, acc);
            acc = ffma2(cx2[p], vx, acc);
            float lo, hi;
            unpack2(acc, lo, hi);
            mnLo[p] = fminf(mnLo[p], lo);
            mnHi[p] = fminf(mnHi[p], hi);
        }
    }

    // Store partial d2 (add |s|^2 now so the reduce is a pure min+sum).
    float* part = g_part + ((size_t)ts * BATCH + b) * NPTS;
#pragma unroll
    for (int p = 0; p < ILP; p++) {
        int n = src0 + p * THREADS + tid;
        part[n] = fminf(mnLo[p], mnHi[p]) + s2[p];
    }
}

__global__ __launch_bounds__(1024) void reduce_kernel(float* __restrict__ out) {
    __shared__ float sh[1024];
    const int b = blockIdx.x;
    float s = 0.0f;
    for (int i = threadIdx.x; i < NPTS; i += 1024) {
        float m = g_part[(size_t)b * NPTS + i];  // ts = 0
#pragma unroll
        for (int t = 1; t < TSPLIT; t++)
            m = fminf(m, g_part[((size_t)t * BATCH + b) * NPTS + i]);
        s += m;
    }
    sh[threadIdx.x] = s;
    __syncthreads();
    for (int o = 512; o > 0; o >>= 1) {
        if (threadIdx.x < o) sh[threadIdx.x] += sh[threadIdx.x + o];
        __syncthreads();
    }
    if (threadIdx.x == 0) out[b] = sh[0] * (1.0f / (3.0f * NPTS));
}

extern "C" void kernel_launch(void* const* d_in, const int* in_sizes, int n_in,
                              void* d_out, int out_size) {
    const float* src = (const float*)d_in[0];  // [B,3,N]
    const float* tgt = (const float*)d_in[1];  // [B,3,M]
    float* out = (float*)d_out;                // [B]

    dim3 grid(TSPLIT, SRC_CHUNKS, BATCH);      // 8 x 8 x 8 = 512 blocks
    nn_kernel<<<grid, THREADS>>>(src, tgt);
    reduce_kernel<<<BATCH, 1024>>>(out);
}

// round 4
// speedup vs baseline: 1.8026x; 1.0643x over previous
#include <cuda_runtime.h>
#include <cstdint>

// KDPointToPointLoss: loss[b] = (1/(3N)) * sum_n min_m ||s[b,:,n] - t[b,:,m]||^2
// B=8, C=3, N=M=4096 (fixed by dataset).
//
// score(n,m) = |t_m|^2 - 2 s_n.t_m (monotone in d2). Targets packed in smem as
// f32x2 pairs; inner loop uses fma.rn.f32x2 (FFMA2: 2 fp32 FMAs/issue slot,
// effective rt~3 due to 3x 64-bit operand RF banking — still beats scalar).
// Grid (tgt x src x batch) = 16x8x8 = 1024 blocks for wave balance; private
// partial slots -> no init pass, no atomics, deterministic. Two-stage reduce.

#define BATCH 8
#define NPTS  4096
#define MPTS  4096

#define THREADS   128
#define ILP       4                       // source points per thread
#define SRC_PER_BLOCK (THREADS * ILP)     // 512
#define SRC_CHUNKS (NPTS / SRC_PER_BLOCK) // 8
#define TSPLIT    16                      // target splits
#define TC        (MPTS / TSPLIT)         // 256 targets per block
#define TC2       (TC / 2)                // 128 packed pairs

#define RSLICES   8                       // point-slices per batch in reduce stage1
#define RPTS      (NPTS / RSLICES)        // 512 points per stage1 block

__device__ float g_part[TSPLIT * BATCH * NPTS];   // partial min d2 per (ts,b,n)
__device__ float g_s1[BATCH * RSLICES];           // stage1 partial sums

__device__ __forceinline__ unsigned long long ffma2(
    unsigned long long a, unsigned long long b, unsigned long long c) {
    unsigned long long d;
    asm("fma.rn.f32x2 %0, %1, %2, %3;" : "=l"(d) : "l"(a), "l"(b), "l"(c));
    return d;
}
__device__ __forceinline__ unsigned long long pack2(float lo, float hi) {
    unsigned long long r;
    asm("mov.b64 %0, {%1, %2};" : "=l"(r) : "f"(lo), "f"(hi));
    return r;
}
__device__ __forceinline__ void unpack2(unsigned long long v, float& lo, float& hi) {
    asm("mov.b64 {%0, %1}, %2;" : "=f"(lo), "=f"(hi) : "l"(v));
}

__global__ __launch_bounds__(THREADS) void nn_kernel(
    const float* __restrict__ src, const float* __restrict__ tgt) {
    __shared__ unsigned long long sx2[TC2], sy2[TC2], sz2[TC2], sw2[TC2];

    const int ts   = blockIdx.x;               // target split
    const int src0 = blockIdx.y * SRC_PER_BLOCK;
    const int b    = blockIdx.z;
    const int tid  = threadIdx.x;
    const int tgt0 = ts * TC;

    // Cooperative packed load of this target chunk (TC2 == THREADS -> 1 iter).
    const float2* tx = (const float2*)(tgt + (size_t)b * 3 * MPTS + 0 * MPTS + tgt0);
    const float2* ty = (const float2*)(tgt + (size_t)b * 3 * MPTS + 1 * MPTS + tgt0);
    const float2* tz = (const float2*)(tgt + (size_t)b * 3 * MPTS + 2 * MPTS + tgt0);
    for (int j2 = tid; j2 < TC2; j2 += THREADS) {
        float2 x = tx[j2];
        float2 y = ty[j2];
        float2 z = tz[j2];
        float w0 = fmaf(x.x, x.x, fmaf(y.x, y.x, z.x * z.x));
        float w1 = fmaf(x.y, x.y, fmaf(y.y, y.y, z.y * z.y));
        sx2[j2] = pack2(x.x, x.y);
        sy2[j2] = pack2(y.x, y.y);
        sz2[j2] = pack2(z.x, z.y);
        sw2[j2] = pack2(w0, w1);
    }

    // Per-thread source points: packed duplicated coefficients (-2s, -2s).
    const float* sb = src + (size_t)b * 3 * NPTS;
    unsigned long long cx2[ILP], cy2[ILP], cz2[ILP];
    float s2[ILP], mnLo[ILP], mnHi[ILP];
#pragma unroll
    for (int p = 0; p < ILP; p++) {
        int n = src0 + p * THREADS + tid;
        float sx = sb[0 * NPTS + n];
        float sy = sb[1 * NPTS + n];
        float sz = sb[2 * NPTS + n];
        cx2[p] = pack2(-2.0f * sx, -2.0f * sx);
        cy2[p] = pack2(-2.0f * sy, -2.0f * sy);
        cz2[p] = pack2(-2.0f * sz, -2.0f * sz);
        s2[p]  = fmaf(sx, sx, fmaf(sy, sy, sz * sz));
        mnLo[p] = 1e30f;
        mnHi[p] = 1e30f;
    }
    __syncthreads();

    // Main loop: per j2 (2 targets): 4 LDS.64 + ILP*(3 FFMA2 + 2 FMNMX).
#pragma unroll 4
    for (int j2 = 0; j2 < TC2; j2++) {
        unsigned long long vx = sx2[j2];
        unsigned long long vy = sy2[j2];
        unsigned long long vz = sz2[j2];
        unsigned long long vw = sw2[j2];
#pragma unroll
        for (int p = 0; p < ILP; p++) {
            unsigned long long acc = ffma2(cz2[p], vz, vw);
            acc = ffma2(cy2[p], vy, acc);
            acc = ffma2(cx2[p], vx, acc);
            float lo, hi;
            unpack2(acc, lo, hi);
            mnLo[p] = fminf(mnLo[p], lo);
            mnHi[p] = fminf(mnHi[p], hi);
        }
    }

    // Store partial d2 (add |s|^2 now so the reduce is pure min+sum).
    float* part = g_part + ((size_t)ts * BATCH + b) * NPTS;
#pragma unroll
    for (int p = 0; p < ILP; p++) {
        int n = src0 + p * THREADS + tid;
        part[n] = fminf(mnLo[p], mnHi[p]) + s2[p];
    }
}

// Stage 1: grid = (RSLICES, BATCH); each block: min over TSPLIT partials for
// its 512 points, then deterministic block-sum into g_s1.
__global__ __launch_bounds__(256) void reduce1_kernel() {
    __shared__ float sh[256];
    const int sl = blockIdx.x;
    const int b  = blockIdx.y;
    const int i0 = sl * RPTS;
    float s = 0.0f;
    for (int i = threadIdx.x; i < RPTS; i += 256) {
        int n = i0 + i;
        float m = g_part[(size_t)b * NPTS + n];  // ts = 0
#pragma unroll
        for (int t = 1; t < TSPLIT; t++)
            m = fminf(m, g_part[((size_t)t * BATCH + b) * NPTS + n]);
        s += m;
    }
    sh[threadIdx.x] = s;
    __syncthreads();
    for (int o = 128; o > 0; o >>= 1) {
        if (threadIdx.x < o) sh[threadIdx.x] += sh[threadIdx.x + o];
        __syncthreads();
    }
    if (threadIdx.x == 0) g_s1[b * RSLICES + sl] = sh[0];
}

// Stage 2: 8 threads, one per batch; fixed-order sum -> deterministic.
__global__ void reduce2_kernel(float* __restrict__ out) {
    int b = threadIdx.x;
    if (b < BATCH) {
        float s = 0.0f;
#pragma unroll
        for (int t = 0; t < RSLICES; t++) s += g_s1[b * RSLICES + t];
        out[b] = s * (1.0f / (3.0f * NPTS));
    }
}

extern "C" void kernel_launch(void* const* d_in, const int* in_sizes, int n_in,
                              void* d_out, int out_size) {
    const float* src = (const float*)d_in[0];  // [B,3,N]
    const float* tgt = (const float*)d_in[1];  // [B,3,M]
    float* out = (float*)d_out;                // [B]

    dim3 grid(TSPLIT, SRC_CHUNKS, BATCH);      // 16 x 8 x 8 = 1024 blocks
    nn_kernel<<<grid, THREADS>>>(src, tgt);

    dim3 rgrid(RSLICES, BATCH);                // 8 x 8 = 64 blocks
    reduce1_kernel<<<rgrid, 256>>>();
    reduce2_kernel<<<1, 32>>>(out);
}

// round 5
// speedup vs baseline: 1.8196x; 1.0094x over previous
#include <cuda_runtime.h>
#include <cstdint>

// KDPointToPointLoss: loss[b] = (1/(3N)) * sum_n min_m ||s[b,:,n] - t[b,:,m]||^2
// B=8, C=3, N=M=4096 (fixed by dataset).
//
// score(n,m) = |t_m|^2 - 2 s_n.t_m (monotone in d2). Targets packed in smem,
// interleaved as two 16B words per pair -> 2x LDS.128/j2. Inner loop uses
// fma.rn.f32x2 (FFMA2). Grid (tgt x src x batch) = 32x8x8 = 2048 blocks to
// fill the reg-limited 9 blocks/SM. Private partial slots -> no atomics,
// deterministic. Two-stage reduce.

#define BATCH 8
#define NPTS  4096
#define MPTS  4096

#define THREADS   128
#define ILP       4                       // source points per thread
#define SRC_PER_BLOCK (THREADS * ILP)     // 512
#define SRC_CHUNKS (NPTS / SRC_PER_BLOCK) // 8
#define TSPLIT    32                      // target splits
#define TC        (MPTS / TSPLIT)         // 128 targets per block
#define TC2       (TC / 2)                // 64 packed pairs

#define RSLICES   8                       // point-slices per batch in reduce stage1
#define RPTS      (NPTS / RSLICES)        // 512 points per stage1 block

__device__ float g_part[TSPLIT * BATCH * NPTS];   // partial min d2 per (ts,b,n)
__device__ float g_s1[BATCH * RSLICES];           // stage1 partial sums

__device__ __forceinline__ unsigned long long ffma2(
    unsigned long long a, unsigned long long b, unsigned long long c) {
    unsigned long long d;
    asm("fma.rn.f32x2 %0, %1, %2, %3;" : "=l"(d) : "l"(a), "l"(b), "l"(c));
    return d;
}
__device__ __forceinline__ unsigned long long pack2(float lo, float hi) {
    unsigned long long r;
    asm("mov.b64 %0, {%1, %2};" : "=l"(r) : "f"(lo), "f"(hi));
    return r;
}
__device__ __forceinline__ void unpack2(unsigned long long v, float& lo, float& hi) {
    asm("mov.b64 {%0, %1}, %2;" : "=f"(lo), "=f"(hi) : "l"(v));
}

__global__ __launch_bounds__(THREADS) void nn_kernel(
    const float* __restrict__ src, const float* __restrict__ tgt) {
    // Interleaved: sxy[j2] = {packed x pair, packed y pair},
    //              szw[j2] = {packed z pair, packed |t|^2 pair}. 16B -> LDS.128.
    __shared__ ulonglong2 sxy[TC2], szw[TC2];

    const int ts   = blockIdx.x;               // target split
    const int src0 = blockIdx.y * SRC_PER_BLOCK;
    const int b    = blockIdx.z;
    const int tid  = threadIdx.x;
    const int tgt0 = ts * TC;

    // Cooperative packed load of this target chunk (TC2=64 <= THREADS).
    const float2* tx = (const float2*)(tgt + (size_t)b * 3 * MPTS + 0 * MPTS + tgt0);
    const float2* ty = (const float2*)(tgt + (size_t)b * 3 * MPTS + 1 * MPTS + tgt0);
    const float2* tz = (const float2*)(tgt + (size_t)b * 3 * MPTS + 2 * MPTS + tgt0);
    if (tid < TC2) {
        int j2 = tid;
        float2 x = tx[j2];
        float2 y = ty[j2];
        float2 z = tz[j2];
        float w0 = fmaf(x.x, x.x, fmaf(y.x, y.x, z.x * z.x));
        float w1 = fmaf(x.y, x.y, fmaf(y.y, y.y, z.y * z.y));
        sxy[j2] = make_ulonglong2(pack2(x.x, x.y), pack2(y.x, y.y));
        szw[j2] = make_ulonglong2(pack2(z.x, z.y), pack2(w0, w1));
    }

    // Per-thread source points: packed duplicated coefficients (-2s, -2s).
    const float* sb = src + (size_t)b * 3 * NPTS;
    unsigned long long cx2[ILP], cy2[ILP], cz2[ILP];
    float s2[ILP], mnLo[ILP], mnHi[ILP];
#pragma unroll
    for (int p = 0; p < ILP; p++) {
        int n = src0 + p * THREADS + tid;
        float sx = sb[0 * NPTS + n];
        float sy = sb[1 * NPTS + n];
        float sz = sb[2 * NPTS + n];
        cx2[p] = pack2(-2.0f * sx, -2.0f * sx);
        cy2[p] = pack2(-2.0f * sy, -2.0f * sy);
        cz2[p] = pack2(-2.0f * sz, -2.0f * sz);
        s2[p]  = fmaf(sx, sx, fmaf(sy, sy, sz * sz));
        mnLo[p] = 1e30f;
        mnHi[p] = 1e30f;
    }
    __syncthreads();

    // Main loop: per j2 (2 targets): 2 LDS.128 + ILP*(3 FFMA2 + 2 FMNMX).
#pragma unroll 4
    for (int j2 = 0; j2 < TC2; j2++) {
        ulonglong2 vxy = sxy[j2];
        ulonglong2 vzw = szw[j2];
#pragma unroll
        for (int p = 0; p < ILP; p++) {
            unsigned long long acc = ffma2(cz2[p], vzw.x, vzw.y);
            acc = ffma2(cy2[p], vxy.y, acc);
            acc = ffma2(cx2[p], vxy.x, acc);
            float lo, hi;
            unpack2(acc, lo, hi);
            mnLo[p] = fminf(mnLo[p], lo);
            mnHi[p] = fminf(mnHi[p], hi);
        }
    }

    // Store partial d2 (add |s|^2 now so the reduce is pure min+sum).
    float* part = g_part + ((size_t)ts * BATCH + b) * NPTS;
#pragma unroll
    for (int p = 0; p < ILP; p++) {
        int n = src0 + p * THREADS + tid;
        part[n] = fminf(mnLo[p], mnHi[p]) + s2[p];
    }
}

// Stage 1: grid = (RSLICES, BATCH); min over TSPLIT partials, block-sum.
__global__ __launch_bounds__(256) void reduce1_kernel() {
    __shared__ float sh[256];
    const int sl = blockIdx.x;
    const int b  = blockIdx.y;
    const int i0 = sl * RPTS;
    float s = 0.0f;
    for (int i = threadIdx.x; i < RPTS; i += 256) {
        int n = i0 + i;
        float m = g_part[(size_t)b * NPTS + n];  // ts = 0
#pragma unroll
        for (int t = 1; t < TSPLIT; t++)
            m = fminf(m, g_part[((size_t)t * BATCH + b) * NPTS + n]);
        s += m;
    }
    sh[threadIdx.x] = s;
    __syncthreads();
    for (int o = 128; o > 0; o >>= 1) {
        if (threadIdx.x < o) sh[threadIdx.x] += sh[threadIdx.x + o];
        __syncthreads();
    }
    if (threadIdx.x == 0) g_s1[b * RSLICES + sl] = sh[0];
}

// Stage 2: 8 threads, one per batch; fixed-order sum -> deterministic.
__global__ void reduce2_kernel(float* __restrict__ out) {
    int b = threadIdx.x;
    if (b < BATCH) {
        float s = 0.0f;
#pragma unroll
        for (int t = 0; t < RSLICES; t++) s += g_s1[b * RSLICES + t];
        out[b] = s * (1.0f / (3.0f * NPTS));
    }
}

extern "C" void kernel_launch(void* const* d_in, const int* in_sizes, int n_in,
                              void* d_out, int out_size) {
    const float* src = (const float*)d_in[0];  // [B,3,N]
    const float* tgt = (const float*)d_in[1];  // [B,3,M]
    float* out = (float*)d_out;                // [B]

    dim3 grid(TSPLIT, SRC_CHUNKS, BATCH);      // 32 x 8 x 8 = 2048 blocks
    nn_kernel<<<grid, THREADS>>>(src, tgt);

    dim3 rgrid(RSLICES, BATCH);                // 8 x 8 = 64 blocks
    reduce1_kernel<<<rgrid, 256>>>();
    reduce2_kernel<<<1, 32>>>(out);
}